// round 13
// baseline (speedup 1.0000x reference)
#include <cuda_runtime.h>
#include <cuda_fp16.h>
#include <cuda_bf16.h>
#include <string.h>

// out[v] = (ds_out[v] + sum_{edges (v<-u)} ds_in[u]) / (1 + in_degree(v))
// Inputs (metadata order): ds_in [100000,128] f32, ds_out [100000,128] f32,
//                          layer_edge_index [2,625000] int32 OR int64 (runtime-
//                          detected; JAX default config downcasts int64->int32).
// Output: [100000,128] f32.
//
// Pipeline: convert(+zero,+detect) -> bucket fill -> dual-edge pull.
// ds_in is mirrored to fp16 (L2-resident, halves gather bytes; adds ~2e-4 rel
// err vs 1e-3 tolerance). Pull processes two edges per warp iteration with 16
// lanes x uint4(8 fp16) each. Merge: each lane KEEPS the quad it stores and
// TRANSMITS the quad its xor-16 partner stores (R11 bug: transmitting the
// kept quad mixes different features — partner keeps the complementary quad).

#define N_NODES 100000
#define D_FEAT  128
#define N_EDGES 625000
#define BUCKET_CAP 64

struct __align__(16) Half8 { __half2 a, b, c, d; };   // 8 fp16 = 16 bytes

// Scratch (no allocations allowed; __device__ globals are the sanctioned path)
__device__ int g_cnt[N_NODES];
__device__ int g_bucket[N_NODES * BUCKET_CAP];
__device__ Half8 g_ds16[N_NODES * D_FEAT / 8];        // 25.6 MB fp16 mirror
__device__ int g_idx_is_i64 = 1;                      // cleared iff int32 detected

__device__ __forceinline__ __half2 u32_as_h2(unsigned u) {
    __half2 h; memcpy(&h, &u, 4); return h;
}

// ---------------------------------------------------------------------------
// K1: fp32 -> fp16 mirror of ds_in; also zeroes per-node counters and detects
// the edge-index dtype (threads 0..63 each sample one int64-interpreted value;
// int32 data packs two indices per sample -> out of range unless the high
// word is node 0, so at least one of 64 samples flags it with certainty.
// Exchanges are identical every call -> deterministic).
// ---------------------------------------------------------------------------
__global__ void __launch_bounds__(256)
convert_kernel(const float* __restrict__ ds_in, const void* __restrict__ edge_index) {
    int i = blockIdx.x * blockDim.x + threadIdx.x;       // 1.6M threads
    if (i < 64) {
        const long long* p64 = (const long long*)edge_index;
        long long v = p64[i];
        if (v < 0 || v >= N_NODES) atomicExch(&g_idx_is_i64, 0);
    }
    if (i < N_NODES) g_cnt[i] = 0;
    const int n8 = N_NODES * D_FEAT / 8;
    if (i >= n8) return;
    float4 a = __ldcs(reinterpret_cast<const float4*>(ds_in) + 2 * i);
    float4 b = __ldcs(reinterpret_cast<const float4*>(ds_in) + 2 * i + 1);
    Half8 h;
    h.a = __float22half2_rn(make_float2(a.x, a.y));
    h.b = __float22half2_rn(make_float2(a.z, a.w));
    h.c = __float22half2_rn(make_float2(b.x, b.y));
    h.d = __float22half2_rn(make_float2(b.z, b.w));
    g_ds16[i] = h;
}

// ---------------------------------------------------------------------------
// K2: bucket fill. One thread per edge: append src id to recv's bucket.
// In-degree is Binomial(625K, 1e-5) ~ Poisson(6.25); max over 100K nodes is
// ~22-25, so BUCKET_CAP=64 is unreachable in practice (guard kept for safety).
// Bucket order is race-dependent but the summed SET per node is deterministic.
// ---------------------------------------------------------------------------
__global__ void __launch_bounds__(256)
fill_kernel(const void* __restrict__ edge_index) {
    int e = blockIdx.x * blockDim.x + threadIdx.x;
    if (e >= N_EDGES) return;

    int r, s;
    if (g_idx_is_i64) {
        const long long* p = (const long long*)edge_index;
        r = (int)__ldg(p + e);
        s = (int)__ldg(p + N_EDGES + e);
    } else {
        const int* p = (const int*)edge_index;
        r = __ldg(p + e);
        s = __ldg(p + N_EDGES + e);
    }

    int pos = atomicAdd(&g_cnt[r], 1);
    if (pos < BUCKET_CAP) {
        g_bucket[r * BUCKET_CAP + pos] = s;
    }
}

// ---------------------------------------------------------------------------
// K3: dual-edge pull + fused epilogue. One warp per node. Lanes 0-15 process
// edge e, lanes 16-31 edge e+1; lane (16*h + c) loads uint4 #c (features
// [8c, 8c+8)) of its edge's source row -> one LDG.128 per lane, 256B per edge.
// fp32 accumulation in 8 regs/lane.
// Merge (4 shfl_xor): lane (h,c) stores feats [8c+4h, 8c+4h+4). It KEEPS
// that quad and TRANSMITS the other quad (which is exactly what its xor-16
// partner stores). r = keep + shfl_xor(tx, 16).
// ---------------------------------------------------------------------------
__global__ void __launch_bounds__(256)
pull_kernel(const float* __restrict__ ds_out, float* __restrict__ out) {
    int v = (blockIdx.x * blockDim.x + threadIdx.x) >> 5;
    if (v >= N_NODES) return;
    int lane = threadIdx.x & 31;
    int half = lane >> 4;
    int c    = lane & 15;

    int cnt = g_cnt[v];                      // broadcast load (same addr per warp)
    int deg = min(cnt, BUCKET_CAP);
    const int* bucket = g_bucket + v * BUCKET_CAP;

    int sid = 0;
    if (lane < deg) sid = __ldg(bucket + lane);   // ids for edges 0..31

    float a0=0.f,a1=0.f,a2=0.f,a3=0.f,a4=0.f,a5=0.f,a6=0.f,a7=0.f;
    const uint4* ds16 = reinterpret_cast<const uint4*>(g_ds16);

    if (deg <= 32) {                         // virtually always
        int pairs = deg & ~1;                // unconditional paired iterations
        for (int e = 0; e < pairs; e += 2) {
            int s = __shfl_sync(0xFFFFFFFFu, sid, e + half);
            uint4 raw = __ldg(ds16 + (size_t)s * (D_FEAT / 8) + c);
            float2 f0 = __half22float2(u32_as_h2(raw.x));
            float2 f1 = __half22float2(u32_as_h2(raw.y));
            float2 f2 = __half22float2(u32_as_h2(raw.z));
            float2 f3 = __half22float2(u32_as_h2(raw.w));
            a0 += f0.x; a1 += f0.y; a2 += f1.x; a3 += f1.y;
            a4 += f2.x; a5 += f2.y; a6 += f3.x; a7 += f3.y;
        }
        if (deg & 1) {                       // odd tail: half 0 only
            int s = __shfl_sync(0xFFFFFFFFu, sid, deg - 1);
            if (half == 0) {
                uint4 raw = __ldg(ds16 + (size_t)s * (D_FEAT / 8) + c);
                float2 f0 = __half22float2(u32_as_h2(raw.x));
                float2 f1 = __half22float2(u32_as_h2(raw.y));
                float2 f2 = __half22float2(u32_as_h2(raw.z));
                float2 f3 = __half22float2(u32_as_h2(raw.w));
                a0 += f0.x; a1 += f0.y; a2 += f1.x; a3 += f1.y;
                a4 += f2.x; a5 += f2.y; a6 += f3.x; a7 += f3.y;
            }
        }
    } else {                                 // safety path (deg > 32)
        for (int e = 0; e < deg; e += 2) {
            int idx = e + half;
            if (idx < deg) {
                int s = __ldg(bucket + idx);
                uint4 raw = __ldg(ds16 + (size_t)s * (D_FEAT / 8) + c);
                float2 f0 = __half22float2(u32_as_h2(raw.x));
                float2 f1 = __half22float2(u32_as_h2(raw.y));
                float2 f2 = __half22float2(u32_as_h2(raw.z));
                float2 f3 = __half22float2(u32_as_h2(raw.w));
                a0 += f0.x; a1 += f0.y; a2 += f1.x; a3 += f1.y;
                a4 += f2.x; a5 += f2.y; a6 += f3.x; a7 += f3.y;
            }
        }
    }

    // Merge: keep = my stored quad (h ? hi : lo); tx = the quad my partner
    // stores (h ? lo : hi). Partner's shfl delivers its tx = partial for MY
    // quad. Verified: lane(0,c) keeps a0-a3, sends a4-a7, receives partner's
    // a0-a3 partial -> full sum of feats [8c,8c+4). Symmetric for half=1.
    float kx = half ? a4 : a0,  tx = half ? a0 : a4;
    float ky = half ? a5 : a1,  ty = half ? a1 : a5;
    float kz = half ? a6 : a2,  tz = half ? a2 : a6;
    float kw = half ? a7 : a3,  tw = half ? a3 : a7;
    float rx = kx + __shfl_xor_sync(0xFFFFFFFFu, tx, 16);
    float ry = ky + __shfl_xor_sync(0xFFFFFFFFu, ty, 16);
    float rz = kz + __shfl_xor_sync(0xFFFFFFFFu, tz, 16);
    float rw = kw + __shfl_xor_sync(0xFFFFFFFFu, tw, 16);

    int f4 = 2 * c + half;                   // output float4 index

    const float4* drow = reinterpret_cast<const float4*>(ds_out + (size_t)v * D_FEAT);
    float4 d = __ldcs(drow + f4);
    float inv = 1.0f / (float)(cnt + 1);
    float4 o;
    o.x = (d.x + rx) * inv;
    o.y = (d.y + ry) * inv;
    o.z = (d.z + rz) * inv;
    o.w = (d.w + rw) * inv;
    __stcs(reinterpret_cast<float4*>(out + (size_t)v * D_FEAT) + f4, o);
}

// ---------------------------------------------------------------------------
extern "C" void kernel_launch(void* const* d_in, const int* in_sizes, int n_in,
                              void* d_out, int out_size) {
    const float* ds_in  = (const float*)d_in[0];
    const float* ds_out = (const float*)d_in[1];
    const void*  edge_index = d_in[2];
    float* out = (float*)d_out;

    {   // fp16 mirror + zero counters + dtype detect
        int threads = 256;
        int n8 = N_NODES * D_FEAT / 8;                 // 1.6M
        int blocks = (n8 + threads - 1) / threads;
        convert_kernel<<<blocks, threads>>>(ds_in, edge_index);
    }
    {   // bucket fill: one thread per edge
        int threads = 256;
        int blocks = (N_EDGES + threads - 1) / threads;
        fill_kernel<<<blocks, threads>>>(edge_index);
    }
    {   // dual-edge pull + epilogue: one warp per node
        int threads = 256;
        int blocks = (N_NODES + 7) / 8;                // 12500
        pull_kernel<<<blocks, threads>>>(ds_out, out);
    }
}

// round 14
// speedup vs baseline: 1.0482x; 1.0482x over previous
#include <cuda_runtime.h>
#include <cuda_fp16.h>
#include <cuda_bf16.h>
#include <string.h>

// out[v] = (ds_out[v] + sum_{edges (v<-u)} ds_in[u]) / (1 + in_degree(v))
// Inputs (metadata order): ds_in [100000,128] f32, ds_out [100000,128] f32,
//                          layer_edge_index [2,625000] int32 (proven: the R3
//                          int64 interpretation produced OOB faults; JAX's
//                          default x64=off config downcast the reference's
//                          int64 randint to int32, and the dataset is fixed).
// Output: [100000,128] f32.
//
// 2-launch pipeline:
//  K1 fused: convert blocks mirror ds_in to fp16 (DRAM-streaming) WHILE fill
//            blocks bucket edges by recv (L2 atomics) — complementary
//            resources overlap. No zero pass: pull resets g_cnt after use.
//  K2 pull:  dual-edge gather (2 edges/warp-iter, 16 lanes x uint4 = 8 fp16),
//            fp32 accumulation, #pragma unroll 4 for MLP (R13 regression was
//            the missing unroll -> MLP=1), fused ds_out add + mean + store.

#define N_NODES 100000
#define D_FEAT  128
#define N_EDGES 625000
#define BUCKET_CAP 64

#define CONV_BLOCKS 6250           /* 1.6M uint4 / 256 exactly */
#define FILL_BLOCKS ((N_EDGES + 255) / 256)

struct __align__(16) Half8 { __half2 a, b, c, d; };   // 8 fp16 = 16 bytes

// Scratch (no allocations allowed; __device__ globals are the sanctioned path)
__device__ int g_cnt[N_NODES];                        // zero-init; pull re-zeros
__device__ int g_bucket[N_NODES * BUCKET_CAP];
__device__ Half8 g_ds16[N_NODES * D_FEAT / 8];        // 25.6 MB fp16 mirror

__device__ __forceinline__ __half2 u32_as_h2(unsigned u) {
    __half2 h; memcpy(&h, &u, 4); return h;
}

// ---------------------------------------------------------------------------
// K1: fused prep.
//  blocks [0, CONV_BLOCKS): fp32 -> fp16 mirror, 8 feats/thread (exact cover).
//  blocks [CONV_BLOCKS, +FILL_BLOCKS): bucket fill, 1 edge/thread.
// g_cnt starts zero on every call: static zero-init before the first call,
// and pull_kernel resets each counter after consuming it on every replay.
// In-degree ~ Poisson(6.25), max over 100K nodes ~22-25; CAP=64 is a guard.
// ---------------------------------------------------------------------------
__global__ void __launch_bounds__(256)
prep_kernel(const float* __restrict__ ds_in, const int* __restrict__ edge_index) {
    if (blockIdx.x < CONV_BLOCKS) {
        int i = blockIdx.x * 256 + threadIdx.x;          // < 1.6M exactly
        float4 a = __ldcs(reinterpret_cast<const float4*>(ds_in) + 2 * i);
        float4 b = __ldcs(reinterpret_cast<const float4*>(ds_in) + 2 * i + 1);
        Half8 h;
        h.a = __float22half2_rn(make_float2(a.x, a.y));
        h.b = __float22half2_rn(make_float2(a.z, a.w));
        h.c = __float22half2_rn(make_float2(b.x, b.y));
        h.d = __float22half2_rn(make_float2(b.z, b.w));
        g_ds16[i] = h;
    } else {
        int e = (blockIdx.x - CONV_BLOCKS) * 256 + threadIdx.x;
        if (e < N_EDGES) {
            int r = __ldg(edge_index + e);               // row 0: recv
            int s = __ldg(edge_index + N_EDGES + e);     // row 1: src
            int pos = atomicAdd(&g_cnt[r], 1);
            if (pos < BUCKET_CAP) {
                g_bucket[r * BUCKET_CAP + pos] = s;
            }
        }
    }
}

// ---------------------------------------------------------------------------
// K2: dual-edge pull + fused epilogue. One warp per node. Lanes 0-15 process
// edge e, lanes 16-31 edge e+1; lane (16*h + c) loads uint4 #c (features
// [8c, 8c+8)) of its edge's source row -> one LDG.128 per lane, 256B/edge.
// unroll 4 lets ptxas front-batch 4 independent LDGs (MLP=4; without it the
// FADD->LDG chain serializes at MLP=1 — the R13 regression).
// Merge (4 shfl_xor): lane (h,c) stores feats [8c+4h,+4). It KEEPS that quad
// and TRANSMITS the quad its xor-16 partner stores.
// After use, lane 0 resets g_cnt[v] so the next replay starts zeroed.
// ---------------------------------------------------------------------------
__global__ void __launch_bounds__(256)
pull_kernel(const float* __restrict__ ds_out, float* __restrict__ out) {
    int v = (blockIdx.x * blockDim.x + threadIdx.x) >> 5;
    if (v >= N_NODES) return;
    int lane = threadIdx.x & 31;
    int half = lane >> 4;
    int c    = lane & 15;

    int cnt = g_cnt[v];                      // broadcast load (same addr per warp)
    int deg = min(cnt, BUCKET_CAP);
    const int* bucket = g_bucket + v * BUCKET_CAP;

    int sid = 0;
    if (lane < deg) sid = __ldg(bucket + lane);   // ids for edges 0..31

    if (lane == 0) g_cnt[v] = 0;             // reset for next replay

    float a0=0.f,a1=0.f,a2=0.f,a3=0.f,a4=0.f,a5=0.f,a6=0.f,a7=0.f;
    const uint4* ds16 = reinterpret_cast<const uint4*>(g_ds16);

    if (deg <= 32) {                         // virtually always
        int pairs = deg & ~1;
        #pragma unroll 4
        for (int e = 0; e < pairs; e += 2) {
            int s = __shfl_sync(0xFFFFFFFFu, sid, e + half);
            uint4 raw = __ldg(ds16 + (size_t)s * (D_FEAT / 8) + c);
            float2 f0 = __half22float2(u32_as_h2(raw.x));
            float2 f1 = __half22float2(u32_as_h2(raw.y));
            float2 f2 = __half22float2(u32_as_h2(raw.z));
            float2 f3 = __half22float2(u32_as_h2(raw.w));
            a0 += f0.x; a1 += f0.y; a2 += f1.x; a3 += f1.y;
            a4 += f2.x; a5 += f2.y; a6 += f3.x; a7 += f3.y;
        }
        if (deg & 1) {                       // odd tail: half 0 only
            int s = __shfl_sync(0xFFFFFFFFu, sid, deg - 1);
            if (half == 0) {
                uint4 raw = __ldg(ds16 + (size_t)s * (D_FEAT / 8) + c);
                float2 f0 = __half22float2(u32_as_h2(raw.x));
                float2 f1 = __half22float2(u32_as_h2(raw.y));
                float2 f2 = __half22float2(u32_as_h2(raw.z));
                float2 f3 = __half22float2(u32_as_h2(raw.w));
                a0 += f0.x; a1 += f0.y; a2 += f1.x; a3 += f1.y;
                a4 += f2.x; a5 += f2.y; a6 += f3.x; a7 += f3.y;
            }
        }
    } else {                                 // safety path (deg > 32)
        for (int e = 0; e < deg; e += 2) {
            int idx = e + half;
            if (idx < deg) {
                int s = __ldg(bucket + idx);
                uint4 raw = __ldg(ds16 + (size_t)s * (D_FEAT / 8) + c);
                float2 f0 = __half22float2(u32_as_h2(raw.x));
                float2 f1 = __half22float2(u32_as_h2(raw.y));
                float2 f2 = __half22float2(u32_as_h2(raw.z));
                float2 f3 = __half22float2(u32_as_h2(raw.w));
                a0 += f0.x; a1 += f0.y; a2 += f1.x; a3 += f1.y;
                a4 += f2.x; a5 += f2.y; a6 += f3.x; a7 += f3.y;
            }
        }
    }

    // Merge: keep = my stored quad (h ? hi : lo); tx = partner's stored quad
    // (h ? lo : hi). Partner's shfl delivers the partial for MY quad.
    float kx = half ? a4 : a0,  tx = half ? a0 : a4;
    float ky = half ? a5 : a1,  ty = half ? a1 : a5;
    float kz = half ? a6 : a2,  tz = half ? a2 : a6;
    float kw = half ? a7 : a3,  tw = half ? a3 : a7;
    float rx = kx + __shfl_xor_sync(0xFFFFFFFFu, tx, 16);
    float ry = ky + __shfl_xor_sync(0xFFFFFFFFu, ty, 16);
    float rz = kz + __shfl_xor_sync(0xFFFFFFFFu, tz, 16);
    float rw = kw + __shfl_xor_sync(0xFFFFFFFFu, tw, 16);

    int f4 = 2 * c + half;                   // output float4 index

    const float4* drow = reinterpret_cast<const float4*>(ds_out + (size_t)v * D_FEAT);
    float4 d = __ldcs(drow + f4);
    float inv = 1.0f / (float)(cnt + 1);
    float4 o;
    o.x = (d.x + rx) * inv;
    o.y = (d.y + ry) * inv;
    o.z = (d.z + rz) * inv;
    o.w = (d.w + rw) * inv;
    __stcs(reinterpret_cast<float4*>(out + (size_t)v * D_FEAT) + f4, o);
}

// ---------------------------------------------------------------------------
extern "C" void kernel_launch(void* const* d_in, const int* in_sizes, int n_in,
                              void* d_out, int out_size) {
    const float* ds_in  = (const float*)d_in[0];
    const float* ds_out = (const float*)d_in[1];
    const int*   edge_index = (const int*)d_in[2];
    float* out = (float*)d_out;

    // K1: fused convert + fill (overlapping DRAM streaming and L2 atomics)
    prep_kernel<<<CONV_BLOCKS + FILL_BLOCKS, 256>>>(ds_in, edge_index);

    // K2: dual-edge pull + epilogue: one warp per node
    pull_kernel<<<(N_NODES + 7) / 8, 256>>>(ds_out, out);
}

// round 16
// speedup vs baseline: 1.1974x; 1.1423x over previous
#include <cuda_runtime.h>
#include <cuda_fp16.h>
#include <cuda_bf16.h>
#include <string.h>

// out[v] = (ds_out[v] + sum_{edges (v<-u)} ds_in[u]) / (1 + in_degree(v))
// Inputs (metadata order): ds_in [100000,128] f32, ds_out [100000,128] f32,
//                          layer_edge_index [2,625000] int32 (proven across
//                          passing rounds; JAX x64=off downcast the int64).
// Output: [100000,128] f32.
//
// 2-launch pipeline:
//  K1 prep (fused): convert blocks mirror ds_in to fp16 (DRAM streaming)
//     WHILE fill blocks bucket edges by recv (L2 atomics) — complementary
//     resources overlap. No zero pass: pull resets g_cnt after use.
//  K2 pull: R8-form 32-lane gather (1 edge/iter, lane L owns feats [4L,4L+4),
//     uint2 fp16 load = 8B/lane), unroll 4 for MLP, fp32 accumulation, fused
//     ds_out add + mean + float4 store. R14 measured the dual-edge variant
//     at 46.7us vs this form's 36.9us (short loops: epilogue overhead and
//     reg pressure beat per-iteration savings) — reverted.

#define N_NODES 100000
#define D_FEAT  128
#define N_EDGES 625000
#define BUCKET_CAP 64

#define CONV_BLOCKS 6250           /* 1.6M uint4 / 256 exactly */
#define FILL_BLOCKS ((N_EDGES + 255) / 256)

struct __align__(16) Half8 { __half2 a, b, c, d; };   // 8 fp16 = 16 bytes

// Scratch (no allocations allowed; __device__ globals are the sanctioned path)
__device__ int g_cnt[N_NODES];                        // zero-init; pull re-zeros
__device__ int g_bucket[N_NODES * BUCKET_CAP];
__device__ Half8 g_ds16[N_NODES * D_FEAT / 8];        // 25.6 MB fp16 mirror

__device__ __forceinline__ __half2 u32_as_h2(unsigned u) {
    __half2 h; memcpy(&h, &u, 4); return h;
}

// ---------------------------------------------------------------------------
// K1: fused prep.
//  blocks [0, CONV_BLOCKS): fp32 -> fp16 mirror, 8 feats/thread (exact cover).
//  blocks [CONV_BLOCKS, +FILL_BLOCKS): bucket fill, 1 edge/thread.
// g_cnt starts zero on every call: static zero-init before the first call,
// and pull_kernel resets each counter after consuming it on every replay.
// In-degree ~ Poisson(6.25), max over 100K nodes ~22-25; CAP=64 is a guard.
// ---------------------------------------------------------------------------
__global__ void __launch_bounds__(256)
prep_kernel(const float* __restrict__ ds_in, const int* __restrict__ edge_index) {
    if (blockIdx.x < CONV_BLOCKS) {
        int i = blockIdx.x * 256 + threadIdx.x;          // < 1.6M exactly
        float4 a = __ldcs(reinterpret_cast<const float4*>(ds_in) + 2 * i);
        float4 b = __ldcs(reinterpret_cast<const float4*>(ds_in) + 2 * i + 1);
        Half8 h;
        h.a = __float22half2_rn(make_float2(a.x, a.y));
        h.b = __float22half2_rn(make_float2(a.z, a.w));
        h.c = __float22half2_rn(make_float2(b.x, b.y));
        h.d = __float22half2_rn(make_float2(b.z, b.w));
        g_ds16[i] = h;
    } else {
        int e = (blockIdx.x - CONV_BLOCKS) * 256 + threadIdx.x;
        if (e < N_EDGES) {
            int r = __ldg(edge_index + e);               // row 0: recv
            int s = __ldg(edge_index + N_EDGES + e);     // row 1: src
            int pos = atomicAdd(&g_cnt[r], 1);
            if (pos < BUCKET_CAP) {
                g_bucket[r * BUCKET_CAP + pos] = s;
            }
        }
    }
}

// ---------------------------------------------------------------------------
// K2: pull + fused epilogue (R8 form). One warp per node; lane L owns
// features [4L, 4L+4): one 8-byte fp16 (uint2) load per edge per lane
// (256B/warp/edge, fully coalesced). Source ids preloaded one-per-lane and
// shfl-broadcast. unroll 4 front-batches independent LDGs (MLP~4).
// Lane 0 resets g_cnt[v] after the read so the next replay starts zeroed.
// ---------------------------------------------------------------------------
__global__ void __launch_bounds__(256)
pull_kernel(const float* __restrict__ ds_out, float* __restrict__ out) {
    int v = (blockIdx.x * blockDim.x + threadIdx.x) >> 5;
    if (v >= N_NODES) return;
    int lane = threadIdx.x & 31;

    int cnt = g_cnt[v];                      // broadcast load (same addr per warp)
    int deg = min(cnt, BUCKET_CAP);
    const int* bucket = g_bucket + v * BUCKET_CAP;

    int sid = 0;
    if (lane < deg) sid = __ldg(bucket + lane);   // ids for edges 0..31

    if (lane == 0) g_cnt[v] = 0;             // reset for next replay

    float4 acc = __ldcs(reinterpret_cast<const float4*>(ds_out + (size_t)v * D_FEAT) + lane);

    const uint2* ds16 = reinterpret_cast<const uint2*>(g_ds16);  // 8B = 4 fp16

    int n0 = min(deg, 32);
    #pragma unroll 4
    for (int e = 0; e < n0; e++) {
        int s = __shfl_sync(0xFFFFFFFFu, sid, e);
        // features 4L..4L+3 of row s: uint2 at index s*32 + L
        uint2 raw = __ldg(ds16 + (size_t)s * (D_FEAT / 4) + lane);
        float2 f0 = __half22float2(u32_as_h2(raw.x));
        float2 f1 = __half22float2(u32_as_h2(raw.y));
        acc.x += f0.x; acc.y += f0.y; acc.z += f1.x; acc.w += f1.y;
    }
    // Rare tail (deg > 32): plain bucket loads.
    for (int e = 32; e < deg; e++) {
        int s = __ldg(bucket + e);
        uint2 raw = __ldg(ds16 + (size_t)s * (D_FEAT / 4) + lane);
        float2 f0 = __half22float2(u32_as_h2(raw.x));
        float2 f1 = __half22float2(u32_as_h2(raw.y));
        acc.x += f0.x; acc.y += f0.y; acc.z += f1.x; acc.w += f1.y;
    }

    float inv = 1.0f / (float)(cnt + 1);
    acc.x *= inv; acc.y *= inv; acc.z *= inv; acc.w *= inv;
    __stcs(reinterpret_cast<float4*>(out + (size_t)v * D_FEAT) + lane, acc);
}

// ---------------------------------------------------------------------------
extern "C" void kernel_launch(void* const* d_in, const int* in_sizes, int n_in,
                              void* d_out, int out_size) {
    const float* ds_in  = (const float*)d_in[0];
    const float* ds_out = (const float*)d_in[1];
    const int*   edge_index = (const int*)d_in[2];
    float* out = (float*)d_out;

    // K1: fused convert + fill (overlapping DRAM streaming and L2 atomics)
    prep_kernel<<<CONV_BLOCKS + FILL_BLOCKS, 256>>>(ds_in, edge_index);

    // K2: pull + epilogue: one warp per node, 8 nodes per 256-thread block
    pull_kernel<<<(N_NODES + 7) / 8, 256>>>(ds_out, out);
}